// round 2
// baseline (speedup 1.0000x reference)
#include <cuda_runtime.h>
#include <math.h>
#include <stdint.h>

// Problem constants
#define BB   32            // batch
#define CC   256           // channels (reduction dim)
#define HCH  14            // cropped H
#define PP   196           // cropped pixels per batch (14*14)
#define KCODES 8192        // number of codes
#define COLS 6272          // BB * PP
#define BOW_ELEMS (BB*KCODES)      // 262144
#define CODES_OFF BOW_ELEMS

// GEMM tiling
#define BM 128             // k-rows per CTA tile
#define BN 32              // columns per CTA tile
#define BK 32              // c-slice per smem stage
#define AP 132             // padded pitch for As rows (k dim)
#define BP 34              // padded pitch for Bs rows (col dim)
#define KSPLIT 4           // split k-range across CTAs for load balance
#define CHUNKS_PER_SPLIT ((KCODES/BM)/KSPLIT)   // 16

// Scratch (device globals; no allocations allowed)
__device__ float g_Fc[CC * COLS];      // cropped features, layout [c][col] ~6.4MB
__device__ float g_esq[KCODES];        // sum_c emb^2 (fp64-accumulated)
__device__ float g_fsq[COLS];          // sum_c f^2 per column
__device__ float g_pm[KSPLIT * COLS];  // partial max  per (split, col)
__device__ float g_ps[KSPLIT * COLS];  // partial sumexp per (split, col)
__device__ float g_colm[COLS];         // merged max per col
__device__ float g_colr[COLS];         // merged 1/sumexp per col

// ---------------------------------------------------------------------------
// Build cropped/transposed feature matrix Fc[c][col], col = b*196 + y*14 + x
// ---------------------------------------------------------------------------
__global__ void k_fc(const float* __restrict__ feat) {
    int c   = blockIdx.y;
    int col = blockIdx.x * 256 + threadIdx.x;
    if (col >= COLS) return;
    int b = col / PP;
    int p = col - b * PP;
    int y = p / HCH + 1;
    int x = p - (y - 1) * HCH + 1;
    g_Fc[c * COLS + col] = feat[((size_t)(b * CC + c) * 16 + y) * 16 + x];
}

// e_sq: warp per row, fp64 accumulation
__global__ void k_esq(const float* __restrict__ emb) {
    int w    = (blockIdx.x * blockDim.x + threadIdx.x) >> 5;
    int lane = threadIdx.x & 31;
    if (w >= KCODES) return;
    const float* r = emb + (size_t)w * CC;
    double s = 0.0;
    for (int i = lane; i < CC; i += 32) {
        float v = r[i];
        s += (double)v * (double)v;
    }
    #pragma unroll
    for (int o = 16; o; o >>= 1) s += __shfl_xor_sync(0xFFFFFFFFu, s, o);
    if (lane == 0) g_esq[w] = (float)s;
}

// f_sq per column, fp64 accumulation (coalesced over col)
__global__ void k_fsq() {
    int col = blockIdx.x * 256 + threadIdx.x;
    if (col >= COLS) return;
    double s = 0.0;
    for (int c = 0; c < CC; c++) {
        float v = g_Fc[c * COLS + col];
        s += (double)v * (double)v;
    }
    g_fsq[col] = (float)s;
}

// ---------------------------------------------------------------------------
// Fused GEMM + logits write + online per-column (max, sumexp) partials.
// grid (196 col-tiles, KSPLIT), block 256.
// Thread (ty=tid/16, tx=tid%16) owns 8 k-rows (ty*8..+8) x 2 cols (tx*2..+2).
// Mimics reference rounding: l = -30 * ((f_sq - 2*cross) + e_sq), each step
// rounded separately (no FMA contraction).
// ---------------------------------------------------------------------------
__global__ __launch_bounds__(256, 2) void k_gemm(const float* __restrict__ emb,
                                                 float* __restrict__ out) {
    __shared__ float As[BK * AP];        // [c][k]
    __shared__ float Bs[BK * BP];        // [c][col]
    __shared__ float s_esq[BM];
    __shared__ float redm[BN][16];
    __shared__ float reds[BN][16];

    int tid  = threadIdx.x;
    int tx   = tid & 15;
    int ty   = tid >> 4;
    int col0 = blockIdx.x * BN;
    int split = blockIdx.y;
    float* codes = out + CODES_OFF;

    int colA = col0 + tx * 2;
    int colB = colA + 1;
    float fsqA = g_fsq[colA];
    float fsqB = g_fsq[colB];
    int bA = colA / PP, pA = colA - bA * PP;
    int bN = colB / PP, pB = colB - bN * PP;
    size_t baseA = (size_t)bA * KCODES * PP + pA;
    size_t baseB = (size_t)bN * KCODES * PP + pB;

    float mA = -INFINITY, sA = 0.0f, mB = -INFINITY, sB = 0.0f;

    #pragma unroll 1
    for (int ch = 0; ch < CHUNKS_PER_SPLIT; ++ch) {
        int kbase = (split * CHUNKS_PER_SPLIT + ch) * BM;
        __syncthreads();   // protect s_esq / smem from previous iteration readers
        if (tid < BM) s_esq[tid] = g_esq[kbase + tid];

        float acc[8][2];
        #pragma unroll
        for (int r = 0; r < 8; r++) { acc[r][0] = 0.0f; acc[r][1] = 0.0f; }

        #pragma unroll 1
        for (int cs = 0; cs < CC / BK; ++cs) {
            int c0 = cs * BK;
            __syncthreads();
            // Load As: 128k x 32c, coalesced along c, stored transposed [c][k]
            #pragma unroll
            for (int i = 0; i < 16; i++) {
                int idx = tid + i * 256;
                int kl = idx >> 5, cl = idx & 31;
                As[cl * AP + kl] = emb[(size_t)(kbase + kl) * CC + c0 + cl];
            }
            // Load Bs: 32c x 32col, coalesced along col
            #pragma unroll
            for (int i = 0; i < 4; i++) {
                int idx = tid + i * 256;
                int cl = idx >> 5, coll = idx & 31;
                Bs[cl * BP + coll] = g_Fc[(size_t)(c0 + cl) * COLS + col0 + coll];
            }
            __syncthreads();
            #pragma unroll
            for (int cci = 0; cci < BK; ++cci) {
                float4 a0 = *(const float4*)&As[cci * AP + ty * 8];
                float4 a1 = *(const float4*)&As[cci * AP + ty * 8 + 4];
                float2 bv = *(const float2*)&Bs[cci * BP + tx * 2];
                float a[8] = {a0.x, a0.y, a0.z, a0.w, a1.x, a1.y, a1.z, a1.w};
                #pragma unroll
                for (int r = 0; r < 8; r++) {
                    acc[r][0] = fmaf(a[r], bv.x, acc[r][0]);
                    acc[r][1] = fmaf(a[r], bv.y, acc[r][1]);
                }
            }
        }

        // Epilogue: logits + online softmax partials
        #pragma unroll
        for (int r = 0; r < 8; r++) {
            int kl = ty * 8 + r;
            float esq = s_esq[kl];
            size_t koff = (size_t)(kbase + kl) * PP;
            {
                float t = __fadd_rn(fsqA, __fmul_rn(-2.0f, acc[r][0]));
                float d = __fadd_rn(t, esq);
                float l = __fmul_rn(-30.0f, d);
                codes[baseA + koff] = l;
                if (l > mA) { sA = __fmaf_rn(sA, __expf(mA - l), 1.0f); mA = l; }
                else        { sA += __expf(l - mA); }
            }
            {
                float t = __fadd_rn(fsqB, __fmul_rn(-2.0f, acc[r][1]));
                float d = __fadd_rn(t, esq);
                float l = __fmul_rn(-30.0f, d);
                codes[baseB + koff] = l;
                if (l > mB) { sB = __fmaf_rn(sB, __expf(mB - l), 1.0f); mB = l; }
                else        { sB += __expf(l - mB); }
            }
        }
    }

    // Merge (m,s) across the 16 ty-threads sharing each column
    __syncthreads();
    redm[tx * 2 + 0][ty] = mA; reds[tx * 2 + 0][ty] = sA;
    redm[tx * 2 + 1][ty] = mB; reds[tx * 2 + 1][ty] = sB;
    __syncthreads();
    if (tid < BN) {
        float m = -INFINITY, s = 0.0f;
        #pragma unroll
        for (int i = 0; i < 16; i++) {
            float mi = redm[tid][i], si = reds[tid][i];
            if (mi > m) { s = s * __expf(m - mi) + si; m = mi; }
            else        { s += si * __expf(mi - m); }
        }
        g_pm[split * COLS + col0 + tid] = m;
        g_ps[split * COLS + col0 + tid] = s;
    }
}

// Merge KSPLIT partials per column
__global__ void k_merge() {
    int col = blockIdx.x * 256 + threadIdx.x;
    if (col >= COLS) return;
    float m = -INFINITY, s = 0.0f;
    #pragma unroll
    for (int sp = 0; sp < KSPLIT; sp++) {
        float mi = g_pm[sp * COLS + col], si = g_ps[sp * COLS + col];
        if (mi > m) { s = s * __expf(m - mi) + si; m = mi; }
        else        { s += si * __expf(mi - m); }
    }
    g_colm[col] = m;
    g_colr[col] = 1.0f / s;
}

// ---------------------------------------------------------------------------
// Pass 2: logits -> codes (exp(l-m)*rinv), plus bow[b,k] = max_p codes.
// grid (KCODES/256, BB), block 256 (8 warps x 32 rows each).
// ---------------------------------------------------------------------------
__global__ void k_phase2(float* __restrict__ out) {
    float* codes = out + CODES_OFF;
    float* bow   = out;
    int b    = blockIdx.y;
    int kc   = blockIdx.x;
    int warp = threadIdx.x >> 5;
    int lane = threadIdx.x & 31;

    __shared__ float sm[PP];
    __shared__ float sr[PP];
    for (int i = threadIdx.x; i < PP; i += 256) {
        sm[i] = g_colm[b * PP + i];
        sr[i] = g_colr[b * PP + i];
    }
    __syncthreads();

    #pragma unroll 1
    for (int rr = 0; rr < 32; ++rr) {
        int k = kc * 256 + warp * 32 + rr;
        float* row = codes + ((size_t)b * KCODES + k) * PP;
        float mx = 0.0f;
        for (int j = lane; j < PP; j += 32) {
            float l = row[j];
            float v = expf(__fadd_rn(l, -sm[j])) * sr[j];
            row[j] = v;
            mx = fmaxf(mx, v);
        }
        #pragma unroll
        for (int o = 16; o; o >>= 1) mx = fmaxf(mx, __shfl_xor_sync(0xFFFFFFFFu, mx, o));
        if (lane == 0) bow[(size_t)b * KCODES + k] = mx;
    }
}

// L1-normalize bow per batch
__global__ void k_norm(float* __restrict__ out) {
    __shared__ float red[256];
    int b = blockIdx.x;
    float* r = out + (size_t)b * KCODES;
    float s = 0.0f;
    for (int i = threadIdx.x; i < KCODES; i += 256) s += fabsf(r[i]);
    red[threadIdx.x] = s;
    __syncthreads();
    for (int o = 128; o; o >>= 1) {
        if (threadIdx.x < o) red[threadIdx.x] += red[threadIdx.x + o];
        __syncthreads();
    }
    float tot = fmaxf(red[0], 1e-12f);
    for (int i = threadIdx.x; i < KCODES; i += 256) r[i] = r[i] / tot;
}

extern "C" void kernel_launch(void* const* d_in, const int* in_sizes, int n_in,
                              void* d_out, int out_size) {
    const float* feat = (const float*)d_in[0];   // [32,256,16,16]
    const float* emb  = (const float*)d_in[1];   // [8192,256]
    float* out = (float*)d_out;                  // bow [32,8192] ++ codes [32,8192,14,14]

    k_fc<<<dim3((COLS + 255) / 256, CC), 256>>>(feat);
    k_esq<<<(KCODES * 32) / 256, 256>>>(emb);
    k_fsq<<<(COLS + 255) / 256, 256>>>();
    k_gemm<<<dim3(COLS / BN, KSPLIT), 256>>>(emb, out);
    k_merge<<<(COLS + 255) / 256, 256>>>();
    k_phase2<<<dim3(KCODES / 256, BB), 256>>>(out);
    k_norm<<<BB, 256>>>(out);
}

// round 5
// speedup vs baseline: 1.2076x; 1.2076x over previous
#include <cuda_runtime.h>
#include <cuda_bf16.h>
#include <math.h>
#include <stdint.h>

#define BB   32
#define CC   256
#define HCH  14
#define PP   196
#define KCODES 8192
#define COLS 6272
#define BOW_ELEMS (BB*KCODES)
#define CODES_OFF BOW_ELEMS

#define KC 64                  // bf16 per chunk row = 128B (SW128)
#define NCHUNK 24              // 6 terms * (256/64)
#define TILE_BYTES 16384       // 128 rows * 128B
#define STAGE 32768            // A tile + B tile
#define DSMEM (2*STAGE + 1024)
#define KSEG 16

// ---------------- scratch ----------------
__device__ __nv_bfloat16 g_eh[KCODES*CC], g_em[KCODES*CC], g_el[KCODES*CC];
__device__ __nv_bfloat16 g_fh[COLS*CC],   g_fm[COLS*CC],   g_fl[COLS*CC];
__device__ float g_esq[KCODES];
__device__ float g_fsq[COLS];
__device__ float g_pm[KSEG*COLS];
__device__ float g_ps[KSEG*COLS];
__device__ float g_colm[COLS];
__device__ float g_colr[COLS];

// ---------------- helpers ----------------
__device__ __forceinline__ uint32_t s2u(const void* p) {
    uint32_t a;
    asm("{ .reg .u64 t; cvta.to.shared.u64 t, %1; cvt.u32.u64 %0, t; }" : "=r"(a) : "l"(p));
    return a;
}
#define SWZ(o) ((o) ^ (((o) >> 3) & 0x70))
__device__ __forceinline__ void cp16(uint32_t dst, const void* src) {
    asm volatile("cp.async.cg.shared.global [%0], [%1], 16;" :: "r"(dst), "l"(src));
}
__device__ __forceinline__ void ldsm4(uint32_t* r, uint32_t addr) {
    asm volatile("ldmatrix.sync.aligned.m8n8.x4.shared.b16 {%0,%1,%2,%3}, [%4];"
                 : "=r"(r[0]), "=r"(r[1]), "=r"(r[2]), "=r"(r[3]) : "r"(addr));
}
__device__ __forceinline__ void mma16816(float* c, const uint32_t* a, const uint32_t* b) {
    asm volatile(
        "mma.sync.aligned.m16n8k16.row.col.f32.bf16.bf16.f32 "
        "{%0,%1,%2,%3}, {%4,%5,%6,%7}, {%8,%9}, {%0,%1,%2,%3};"
        : "+f"(c[0]), "+f"(c[1]), "+f"(c[2]), "+f"(c[3])
        : "r"(a[0]), "r"(a[1]), "r"(a[2]), "r"(a[3]), "r"(b[0]), "r"(b[1]));
}

// ---------------- prep: bf16 hi/mid/lo splits ----------------
__global__ void k_prep_e(const float* __restrict__ emb) {
    int idx = blockIdx.x * 256 + threadIdx.x;
    float v = emb[idx];
    __nv_bfloat16 h = __float2bfloat16_rn(v);
    float r1 = v - __bfloat162float(h);
    __nv_bfloat16 m = __float2bfloat16_rn(r1);
    float r2 = r1 - __bfloat162float(m);
    g_eh[idx] = h; g_em[idx] = m; g_el[idx] = __float2bfloat16_rn(r2);
}

__global__ void k_esq(const float* __restrict__ emb) {
    int w = (blockIdx.x * blockDim.x + threadIdx.x) >> 5;
    int lane = threadIdx.x & 31;
    if (w >= KCODES) return;
    const float* r = emb + (size_t)w * CC;
    double s = 0.0;
    for (int i = lane; i < CC; i += 32) { float v = r[i]; s += (double)v * (double)v; }
    #pragma unroll
    for (int o = 16; o; o >>= 1) s += __shfl_xor_sync(0xFFFFFFFFu, s, o);
    if (lane == 0) g_esq[w] = (float)s;
}

// crop + transpose features -> [col][c] bf16 splits
__global__ void k_prep_f(const float* __restrict__ feat) {
    __shared__ float tile[32][33];
    int tx = threadIdx.x, ty = threadIdx.y;
    int col = blockIdx.x * 32 + tx;
    int c   = blockIdx.y * 32 + ty;
    int b = col / PP, p = col - b * PP;
    int y = p / HCH + 1, x = p - (y - 1) * HCH + 1;
    tile[ty][tx] = feat[((size_t)(b * CC + c) * 16 + y) * 16 + x];
    __syncthreads();
    int colw = blockIdx.x * 32 + ty;
    int cw   = blockIdx.y * 32 + tx;
    float v = tile[tx][ty];
    __nv_bfloat16 h = __float2bfloat16_rn(v);
    float r1 = v - __bfloat162float(h);
    __nv_bfloat16 m = __float2bfloat16_rn(r1);
    float r2 = r1 - __bfloat162float(m);
    size_t o = (size_t)colw * CC + cw;
    g_fh[o] = h; g_fm[o] = m; g_fl[o] = __float2bfloat16_rn(r2);
}

__global__ void k_fsq(const float* __restrict__ feat) {
    int col = blockIdx.x * 256 + threadIdx.x;
    if (col >= COLS) return;
    int b = col / PP, p = col - b * PP;
    int y = p / HCH + 1, x = p - (y - 1) * HCH + 1;
    double s = 0.0;
    for (int c = 0; c < CC; c++) {
        float v = feat[((size_t)(b * CC + c) * 16 + y) * 16 + x];
        s += (double)v * (double)v;
    }
    g_fsq[col] = (float)s;
}

// ---------------------------------------------------------------------------
// Warp-MMA GEMM: CTA 128(codes) x 128(cols), 16 warps, warp tile 32x32.
// 6-term bf16x3 emulation, double-buffered cp.async, SW128 smem.
// Epilogue writes logits l = -30*((fsq - 2*cross) + esq).
// ---------------------------------------------------------------------------
__global__ __launch_bounds__(512, 1) void k_mma(float* __restrict__ out) {
    extern __shared__ char dsm[];
    __shared__ float     s_fsq[128];
    __shared__ float     s_esq[128];
    __shared__ long long s_cbase[128];

    int tid = threadIdx.x, lane = tid & 31, wid = tid >> 5;
    int warp_m = wid >> 2, warp_n = wid & 3;
    int col0 = blockIdx.x * 128, krow0 = blockIdx.y * 128;
    float* codes = out + CODES_OFF;
    uint32_t base = (s2u(dsm) + 1023u) & ~1023u;

    if (tid < 128) {
        int col = col0 + tid;
        s_fsq[tid] = g_fsq[col];
        int b = col / PP, p = col - b * PP;
        s_cbase[tid] = (long long)b * KCODES * PP + p;
        s_esq[tid] = g_esq[krow0 + tid];
    }

    float acc[2][4][4];
    #pragma unroll
    for (int mi = 0; mi < 2; mi++)
        #pragma unroll
        for (int ni = 0; ni < 4; ni++)
            #pragma unroll
            for (int q = 0; q < 4; q++) acc[mi][ni][q] = 0.0f;

    // per-thread ldmatrix address components
    int rA = lane & 15, csA = lane >> 4;                      // A: rows m, chunk sel
    int rB = ((lane >> 4) << 3) + (lane & 7), csB = (lane >> 3) & 1;  // B: rows n

    // issue loads for chunk ch into buffer buf
    auto issue = [&](int ch, int buf) {
        int t = ch >> 2, c0 = (ch & 3) * KC;
        int ai = (t == 0) ? 2 : ((t == 2 || t == 3) ? 1 : 0);
        int bi = (t == 1) ? 2 : ((t == 2 || t == 4) ? 1 : 0);
        const __nv_bfloat16* pa = ((ai == 0) ? g_eh : (ai == 1) ? g_em : g_el)
                                  + (size_t)krow0 * CC + c0;
        const __nv_bfloat16* pb = ((bi == 0) ? g_fh : (bi == 1) ? g_fm : g_fl)
                                  + (size_t)col0 * CC + c0;
        uint32_t A0 = base + buf * STAGE, B0 = A0 + TILE_BYTES;
        #pragma unroll
        for (int i = 0; i < 2; i++) {
            int u = tid + i * 512, r = u >> 3, g = u & 7;
            uint32_t off = (uint32_t)(r * 128 + g * 16);
            cp16(A0 + SWZ(off), pa + (size_t)r * CC + g * 8);
            cp16(B0 + SWZ(off), pb + (size_t)r * CC + g * 8);
        }
        asm volatile("cp.async.commit_group;" ::: "memory");
    };

    issue(0, 0);

    #pragma unroll 1
    for (int ch = 0; ch < NCHUNK; ++ch) {
        if (ch < NCHUNK - 1) issue(ch + 1, (ch + 1) & 1);
        if (ch < NCHUNK - 1) asm volatile("cp.async.wait_group 1;" ::: "memory");
        else                 asm volatile("cp.async.wait_group 0;" ::: "memory");
        __syncthreads();

        uint32_t A0 = base + (ch & 1) * STAGE, B0 = A0 + TILE_BYTES;
        #pragma unroll
        for (int s = 0; s < 4; s++) {
            uint32_t a[8], b[8];
            {
                uint32_t off = (uint32_t)((warp_m * 32 + rA) * 128 + (2 * s + csA) * 16);
                ldsm4(a, A0 + SWZ(off));
                uint32_t off2 = (uint32_t)((warp_m * 32 + 16 + rA) * 128 + (2 * s + csA) * 16);
                ldsm4(a + 4, A0 + SWZ(off2));
            }
            {
                uint32_t off = (uint32_t)((warp_n * 32 + rB) * 128 + (2 * s + csB) * 16);
                ldsm4(b, B0 + SWZ(off));
                uint32_t off2 = (uint32_t)((warp_n * 32 + 16 + rB) * 128 + (2 * s + csB) * 16);
                ldsm4(b + 4, B0 + SWZ(off2));
            }
            #pragma unroll
            for (int mi = 0; mi < 2; mi++)
                #pragma unroll
                for (int ni = 0; ni < 4; ni++)
                    mma16816(acc[mi][ni], a + 4 * mi, b + 2 * ni);
        }
        __syncthreads();
    }

    // epilogue: logits from fragments
    #pragma unroll
    for (int mi = 0; mi < 2; mi++) {
        #pragma unroll
        for (int ni = 0; ni < 4; ni++) {
            int krel0 = warp_m * 32 + mi * 16 + (lane >> 2);
            int j0 = warp_n * 32 + ni * 8 + 2 * (lane & 3);
            #pragma unroll
            for (int rr = 0; rr < 2; rr++) {
                int krel = krel0 + rr * 8;
                float esq = s_esq[krel];
                long long koff = (long long)(krow0 + krel) * PP;
                #pragma unroll
                for (int jj = 0; jj < 2; jj++) {
                    int j = j0 + jj;
                    float cross = acc[mi][ni][rr * 2 + jj];
                    float tq = __fadd_rn(s_fsq[j], __fmul_rn(-2.0f, cross));
                    float d  = __fadd_rn(tq, esq);
                    float l  = __fmul_rn(-30.0f, d);
                    codes[s_cbase[j] + koff] = l;
                }
            }
        }
    }
}

// ---------------- pass A: per-column (max,sumexp) partials ----------------
__global__ void k_red(const float* __restrict__ out) {
    const float* codes = out + CODES_OFF;
    int col = blockIdx.x * 128 + threadIdx.x;
    int seg = blockIdx.y;
    int b = col / PP, p = col - b * PP;
    const float* cp = codes + (size_t)b * KCODES * PP + p;
    int k0 = seg * (KCODES / KSEG);
    float m = -INFINITY, s = 0.0f;
    #pragma unroll 4
    for (int k = k0; k < k0 + KCODES / KSEG; k++) {
        float l = cp[(size_t)k * PP];
        if (l > m) { s = __fmaf_rn(s, __expf(m - l), 1.0f); m = l; }
        else       { s += __expf(l - m); }
    }
    g_pm[seg * COLS + col] = m;
    g_ps[seg * COLS + col] = s;
}

__global__ void k_merge() {
    int col = blockIdx.x * 256 + threadIdx.x;
    if (col >= COLS) return;
    float m = -INFINITY, s = 0.0f;
    #pragma unroll
    for (int sp = 0; sp < KSEG; sp++) {
        float mi = g_pm[sp * COLS + col], si = g_ps[sp * COLS + col];
        if (mi > m) { s = s * __expf(m - mi) + si; m = mi; }
        else        { s += si * __expf(mi - m); }
    }
    g_colm[col] = m;
    g_colr[col] = 1.0f / s;
}

// ---------------- pass B: rescale + bow max ----------------
__global__ void k_phase2(float* __restrict__ out) {
    float* codes = out + CODES_OFF;
    float* bow   = out;
    int b = blockIdx.y, kc = blockIdx.x;
    int warp = threadIdx.x >> 5, lane = threadIdx.x & 31;

    __shared__ float sm[PP];
    __shared__ float sr[PP];
    for (int i = threadIdx.x; i < PP; i += 256) {
        sm[i] = g_colm[b * PP + i];
        sr[i] = g_colr[b * PP + i];
    }
    __syncthreads();

    #pragma unroll 1
    for (int rr = 0; rr < 32; ++rr) {
        int k = kc * 256 + warp * 32 + rr;
        float* row = codes + ((size_t)b * KCODES + k) * PP;
        float mx = 0.0f;
        for (int j = lane; j < PP; j += 32) {
            float l = row[j];
            float v = expf(__fadd_rn(l, -sm[j])) * sr[j];
            row[j] = v;
            mx = fmaxf(mx, v);
        }
        #pragma unroll
        for (int o = 16; o; o >>= 1) mx = fmaxf(mx, __shfl_xor_sync(0xFFFFFFFFu, mx, o));
        if (lane == 0) bow[(size_t)b * KCODES + k] = mx;
    }
}

__global__ void k_norm(float* __restrict__ out) {
    __shared__ float red[256];
    int b = blockIdx.x;
    float* r = out + (size_t)b * KCODES;
    float s = 0.0f;
    for (int i = threadIdx.x; i < KCODES; i += 256) s += fabsf(r[i]);
    red[threadIdx.x] = s;
    __syncthreads();
    for (int o = 128; o; o >>= 1) {
        if (threadIdx.x < o) red[threadIdx.x] += red[threadIdx.x + o];
        __syncthreads();
    }
    float tot = fmaxf(red[0], 1e-12f);
    for (int i = threadIdx.x; i < KCODES; i += 256) r[i] = r[i] / tot;
}

extern "C" void kernel_launch(void* const* d_in, const int* in_sizes, int n_in,
                              void* d_out, int out_size) {
    const float* feat = (const float*)d_in[0];   // [32,256,16,16]
    const float* emb  = (const float*)d_in[1];   // [8192,256]
    float* out = (float*)d_out;

    cudaFuncSetAttribute(k_mma, cudaFuncAttributeMaxDynamicSharedMemorySize, DSMEM);

    k_prep_e<<<KCODES * CC / 256, 256>>>(emb);
    k_esq<<<(KCODES * 32) / 256, 256>>>(emb);
    k_prep_f<<<dim3(COLS / 32, CC / 32), dim3(32, 32)>>>(feat);
    k_fsq<<<(COLS + 255) / 256, 256>>>(feat);
    k_mma<<<dim3(COLS / 128, KCODES / 128), 512, DSMEM>>>(out);
    k_red<<<dim3(COLS / 128, KSEG), 128>>>(out);
    k_merge<<<(COLS + 255) / 256, 256>>>();
    k_phase2<<<dim3(KCODES / 256, BB), 256>>>(out);
    k_norm<<<BB, 256>>>(out);
}

// round 6
// speedup vs baseline: 1.3958x; 1.1559x over previous
#include <cuda_runtime.h>
#include <cuda_bf16.h>
#include <math.h>
#include <stdint.h>

#define BB   32
#define CC   256
#define HCH  14
#define PP   196
#define KCODES 8192
#define COLS 6272
#define BOW_ELEMS (BB*KCODES)
#define CODES_OFF BOW_ELEMS

#define KC 64                  // bf16 per chunk row = 128B (SW128)
#define NCHUNK 24              // 6 terms * (256/64)
#define TILE_BYTES 16384       // 128 rows * 128B
#define STAGE 32768            // A tile + B tile
#define NSTAGE 3
#define DSMEM (NSTAGE*STAGE + 1024)
#define KSEG 64                // one segment per 128-row k-tile

// ---------------- scratch ----------------
__device__ __nv_bfloat16 g_eh[KCODES*CC], g_em[KCODES*CC], g_el[KCODES*CC];
__device__ __nv_bfloat16 g_fh[COLS*CC],   g_fm[COLS*CC],   g_fl[COLS*CC];
__device__ float g_esq[KCODES];
__device__ float g_fsq[COLS];
__device__ float g_pm[KSEG*COLS];
__device__ float g_ps[KSEG*COLS];
__device__ float g_colm[COLS];
__device__ float g_colr[COLS];

// ---------------- helpers ----------------
__device__ __forceinline__ uint32_t s2u(const void* p) {
    uint32_t a;
    asm("{ .reg .u64 t; cvta.to.shared.u64 t, %1; cvt.u32.u64 %0, t; }" : "=r"(a) : "l"(p));
    return a;
}
#define SWZ(o) ((o) ^ (((o) >> 3) & 0x70))
__device__ __forceinline__ void cp16(uint32_t dst, const void* src) {
    asm volatile("cp.async.cg.shared.global [%0], [%1], 16;" :: "r"(dst), "l"(src));
}
__device__ __forceinline__ void ldsm4(uint32_t* r, uint32_t addr) {
    asm volatile("ldmatrix.sync.aligned.m8n8.x4.shared.b16 {%0,%1,%2,%3}, [%4];"
                 : "=r"(r[0]), "=r"(r[1]), "=r"(r[2]), "=r"(r[3]) : "r"(addr));
}
__device__ __forceinline__ void mma16816(float* c, const uint32_t* a, const uint32_t* b) {
    asm volatile(
        "mma.sync.aligned.m16n8k16.row.col.f32.bf16.bf16.f32 "
        "{%0,%1,%2,%3}, {%4,%5,%6,%7}, {%8,%9}, {%0,%1,%2,%3};"
        : "+f"(c[0]), "+f"(c[1]), "+f"(c[2]), "+f"(c[3])
        : "r"(a[0]), "r"(a[1]), "r"(a[2]), "r"(a[3]), "r"(b[0]), "r"(b[1]));
}

// ---------------- prep: bf16 hi/mid/lo splits ----------------
__global__ void k_prep_e(const float* __restrict__ emb) {
    int idx = blockIdx.x * 256 + threadIdx.x;
    float v = emb[idx];
    __nv_bfloat16 h = __float2bfloat16_rn(v);
    float r1 = v - __bfloat162float(h);
    __nv_bfloat16 m = __float2bfloat16_rn(r1);
    float r2 = r1 - __bfloat162float(m);
    g_eh[idx] = h; g_em[idx] = m; g_el[idx] = __float2bfloat16_rn(r2);
}

__global__ void k_esq(const float* __restrict__ emb) {
    int w = (blockIdx.x * blockDim.x + threadIdx.x) >> 5;
    int lane = threadIdx.x & 31;
    if (w >= KCODES) return;
    const float* r = emb + (size_t)w * CC;
    double s = 0.0;
    for (int i = lane; i < CC; i += 32) { float v = r[i]; s += (double)v * (double)v; }
    #pragma unroll
    for (int o = 16; o; o >>= 1) s += __shfl_xor_sync(0xFFFFFFFFu, s, o);
    if (lane == 0) g_esq[w] = (float)s;
}

// crop + transpose features -> [col][c] bf16 splits
__global__ void k_prep_f(const float* __restrict__ feat) {
    __shared__ float tile[32][33];
    int tx = threadIdx.x, ty = threadIdx.y;
    int col = blockIdx.x * 32 + tx;
    int c   = blockIdx.y * 32 + ty;
    int b = col / PP, p = col - b * PP;
    int y = p / HCH + 1, x = p - (y - 1) * HCH + 1;
    tile[ty][tx] = feat[((size_t)(b * CC + c) * 16 + y) * 16 + x];
    __syncthreads();
    int colw = blockIdx.x * 32 + ty;
    int cw   = blockIdx.y * 32 + tx;
    float v = tile[tx][ty];
    __nv_bfloat16 h = __float2bfloat16_rn(v);
    float r1 = v - __bfloat162float(h);
    __nv_bfloat16 m = __float2bfloat16_rn(r1);
    float r2 = r1 - __bfloat162float(m);
    size_t o = (size_t)colw * CC + cw;
    g_fh[o] = h; g_fm[o] = m; g_fl[o] = __float2bfloat16_rn(r2);
}

// f_sq: one block per batch, thread = pixel, coalesced loop over channels
__global__ void k_fsq(const float* __restrict__ feat) {
    int b = blockIdx.x, t = threadIdx.x;          // t = y*16+x
    const float* fp = feat + (size_t)b * CC * 256 + t;
    double s = 0.0;
    #pragma unroll 8
    for (int c = 0; c < CC; c++) {
        float v = fp[(size_t)c * 256];
        s += (double)v * (double)v;
    }
    int y = t >> 4, x = t & 15;
    if (y >= 1 && y <= 14 && x >= 1 && x <= 14)
        g_fsq[b * PP + (y - 1) * HCH + (x - 1)] = (float)s;
}

// ---------------------------------------------------------------------------
// Warp-MMA GEMM: CTA 128(codes) x 128(cols), 16 warps, warp tile 32x32.
// 6-term bf16x3 emulation, 3-stage cp.async pipeline, SW128 smem.
// Epilogue writes logits AND per-(ktile,col) partial (max, sumexp).
// ---------------------------------------------------------------------------
__global__ __launch_bounds__(512, 1) void k_mma(float* __restrict__ out) {
    extern __shared__ char dsm[];
    __shared__ float     s_fsq[128];
    __shared__ float     s_esq[128];
    __shared__ long long s_cbase[128];
    __shared__ float     s_rm[4][128];
    __shared__ float     s_rs[4][128];

    int tid = threadIdx.x, lane = tid & 31, wid = tid >> 5;
    int warp_m = wid >> 2, warp_n = wid & 3;
    int col0 = blockIdx.x * 128, krow0 = blockIdx.y * 128;
    float* codes = out + CODES_OFF;
    uint32_t base = (s2u(dsm) + 1023u) & ~1023u;

    if (tid < 128) {
        int col = col0 + tid;
        s_fsq[tid] = g_fsq[col];
        int b = col / PP, p = col - b * PP;
        s_cbase[tid] = (long long)b * KCODES * PP + p;
        s_esq[tid] = g_esq[krow0 + tid];
    }

    float acc[2][4][4];
    #pragma unroll
    for (int mi = 0; mi < 2; mi++)
        #pragma unroll
        for (int ni = 0; ni < 4; ni++)
            #pragma unroll
            for (int q = 0; q < 4; q++) acc[mi][ni][q] = 0.0f;

    int rA = lane & 15, csA = lane >> 4;
    int rB = ((lane >> 4) << 3) + (lane & 7), csB = (lane >> 3) & 1;

    auto issue = [&](int ch, int buf) {
        int t = ch >> 2, c0 = (ch & 3) * KC;
        int ai = (t == 0) ? 2 : ((t == 2 || t == 3) ? 1 : 0);
        int bi = (t == 1) ? 2 : ((t == 2 || t == 4) ? 1 : 0);
        const __nv_bfloat16* pa = ((ai == 0) ? g_eh : (ai == 1) ? g_em : g_el)
                                  + (size_t)krow0 * CC + c0;
        const __nv_bfloat16* pb = ((bi == 0) ? g_fh : (bi == 1) ? g_fm : g_fl)
                                  + (size_t)col0 * CC + c0;
        uint32_t A0 = base + buf * STAGE, B0 = A0 + TILE_BYTES;
        #pragma unroll
        for (int i = 0; i < 2; i++) {
            int u = tid + i * 512, r = u >> 3, g = u & 7;
            uint32_t off = (uint32_t)(r * 128 + g * 16);
            cp16(A0 + SWZ(off), pa + (size_t)r * CC + g * 8);
            cp16(B0 + SWZ(off), pb + (size_t)r * CC + g * 8);
        }
        asm volatile("cp.async.commit_group;" ::: "memory");
    };

    issue(0, 0);
    issue(1, 1);

    #pragma unroll 1
    for (int ch = 0; ch < NCHUNK; ++ch) {
        if (ch < NCHUNK - 1) asm volatile("cp.async.wait_group 1;" ::: "memory");
        else                 asm volatile("cp.async.wait_group 0;" ::: "memory");
        __syncthreads();   // buffer ch%NSTAGE full for all warps; also closes ch-1 compute

        uint32_t A0 = base + (ch % NSTAGE) * STAGE, B0 = A0 + TILE_BYTES;
        #pragma unroll
        for (int s = 0; s < 4; s++) {
            uint32_t a[8], b[8];
            {
                uint32_t off = (uint32_t)((warp_m * 32 + rA) * 128 + (2 * s + csA) * 16);
                ldsm4(a, A0 + SWZ(off));
                uint32_t off2 = (uint32_t)((warp_m * 32 + 16 + rA) * 128 + (2 * s + csA) * 16);
                ldsm4(a + 4, A0 + SWZ(off2));
            }
            {
                uint32_t off = (uint32_t)((warp_n * 32 + rB) * 128 + (2 * s + csB) * 16);
                ldsm4(b, B0 + SWZ(off));
                uint32_t off2 = (uint32_t)((warp_n * 32 + 16 + rB) * 128 + (2 * s + csB) * 16);
                ldsm4(b + 4, B0 + SWZ(off2));
            }
            #pragma unroll
            for (int mi = 0; mi < 2; mi++)
                #pragma unroll
                for (int ni = 0; ni < 4; ni++)
                    mma16816(acc[mi][ni], a + 4 * mi, b + 2 * ni);
        }
        // issue next-next chunk into buffer (ch+2)%NSTAGE; its previous contents
        // (chunk ch-1) were finished by ALL warps before this iteration's barrier.
        if (ch + 2 < NCHUNK) issue(ch + 2, (ch + 2) % NSTAGE);
    }

    // ---- epilogue: logits + partial (max,sumexp) per column ----
    #pragma unroll
    for (int ni = 0; ni < 4; ni++) {
        #pragma unroll
        for (int jj = 0; jj < 2; jj++) {
            int j = warp_n * 32 + ni * 8 + 2 * (lane & 3) + jj;
            float fsq = s_fsq[j];
            long long cb = s_cbase[j];
            float pm = -INFINITY, ps = 0.0f;
            #pragma unroll
            for (int mi = 0; mi < 2; mi++) {
                #pragma unroll
                for (int rr = 0; rr < 2; rr++) {
                    int krel = warp_m * 32 + mi * 16 + (lane >> 2) + rr * 8;
                    float cross = acc[mi][ni][rr * 2 + jj];
                    float tq = __fadd_rn(fsq, __fmul_rn(-2.0f, cross));
                    float d  = __fadd_rn(tq, s_esq[krel]);
                    float l  = __fmul_rn(-30.0f, d);
                    codes[cb + (long long)(krow0 + krel) * PP] = l;
                    if (l > pm) { ps = __fmaf_rn(ps, __expf(pm - l), 1.0f); pm = l; }
                    else        { ps += __expf(l - pm); }
                }
            }
            // reduce over the 8 lanes (lane>>2 = 0..7) sharing column j
            #pragma unroll
            for (int o = 4; o <= 16; o <<= 1) {
                float om = __shfl_xor_sync(0xFFFFFFFFu, pm, o);
                float os = __shfl_xor_sync(0xFFFFFFFFu, ps, o);
                if (om > pm) { ps = ps * __expf(pm - om) + os; pm = om; }
                else         { ps += os * __expf(om - pm); }
            }
            if ((lane >> 2) == 0) { s_rm[warp_m][j] = pm; s_rs[warp_m][j] = ps; }
        }
    }
    __syncthreads();
    if (tid < 128) {
        float m = -INFINITY, s = 0.0f;
        #pragma unroll
        for (int w = 0; w < 4; w++) {
            float mi = s_rm[w][tid], si = s_rs[w][tid];
            if (mi > m) { s = s * __expf(m - mi) + si; m = mi; }
            else        { s += si * __expf(mi - m); }
        }
        g_pm[blockIdx.y * COLS + col0 + tid] = m;
        g_ps[blockIdx.y * COLS + col0 + tid] = s;
    }
}

// ---------------- merge KSEG partials per column ----------------
__global__ void k_merge() {
    int col = blockIdx.x * 256 + threadIdx.x;
    if (col >= COLS) return;
    float m = -INFINITY, s = 0.0f;
    #pragma unroll 8
    for (int sp = 0; sp < KSEG; sp++) {
        float mi = g_pm[sp * COLS + col], si = g_ps[sp * COLS + col];
        if (mi > m) { s = s * __expf(m - mi) + si; m = mi; }
        else        { s += si * __expf(mi - m); }
    }
    g_colm[col] = m;
    g_colr[col] = 1.0f / s;
}

// ---------------- pass B: rescale + bow max ----------------
__global__ void k_phase2(float* __restrict__ out) {
    float* codes = out + CODES_OFF;
    float* bow   = out;
    int b = blockIdx.y, kc = blockIdx.x;
    int warp = threadIdx.x >> 5, lane = threadIdx.x & 31;

    __shared__ float sm[PP];
    __shared__ float sr[PP];
    for (int i = threadIdx.x; i < PP; i += 256) {
        sm[i] = g_colm[b * PP + i];
        sr[i] = g_colr[b * PP + i];
    }
    __syncthreads();

    #pragma unroll 1
    for (int rr = 0; rr < 32; ++rr) {
        int k = kc * 256 + warp * 32 + rr;
        float* row = codes + ((size_t)b * KCODES + k) * PP;
        float mx = 0.0f;
        for (int j = lane; j < PP; j += 32) {
            float l = row[j];
            float v = expf(__fadd_rn(l, -sm[j])) * sr[j];
            row[j] = v;
            mx = fmaxf(mx, v);
        }
        #pragma unroll
        for (int o = 16; o; o >>= 1) mx = fmaxf(mx, __shfl_xor_sync(0xFFFFFFFFu, mx, o));
        if (lane == 0) bow[(size_t)b * KCODES + k] = mx;
    }
}

__global__ void k_norm(float* __restrict__ out) {
    __shared__ float red[256];
    int b = blockIdx.x;
    float* r = out + (size_t)b * KCODES;
    float s = 0.0f;
    for (int i = threadIdx.x; i < KCODES; i += 256) s += fabsf(r[i]);
    red[threadIdx.x] = s;
    __syncthreads();
    for (int o = 128; o; o >>= 1) {
        if (threadIdx.x < o) red[threadIdx.x] += red[threadIdx.x + o];
        __syncthreads();
    }
    float tot = fmaxf(red[0], 1e-12f);
    for (int i = threadIdx.x; i < KCODES; i += 256) r[i] = r[i] / tot;
}

extern "C" void kernel_launch(void* const* d_in, const int* in_sizes, int n_in,
                              void* d_out, int out_size) {
    const float* feat = (const float*)d_in[0];   // [32,256,16,16]
    const float* emb  = (const float*)d_in[1];   // [8192,256]
    float* out = (float*)d_out;

    cudaFuncSetAttribute(k_mma, cudaFuncAttributeMaxDynamicSharedMemorySize, DSMEM);

    k_prep_e<<<KCODES * CC / 256, 256>>>(emb);
    k_esq<<<(KCODES * 32) / 256, 256>>>(emb);
    k_prep_f<<<dim3(COLS / 32, CC / 32), dim3(32, 32)>>>(feat);
    k_fsq<<<BB, 256>>>(feat);
    k_mma<<<dim3(COLS / 128, KCODES / 128), 512, DSMEM>>>(out);
    k_merge<<<(COLS + 255) / 256, 256>>>();
    k_phase2<<<dim3(KCODES / 256, BB), 256>>>(out);
    k_norm<<<BB, 256>>>(out);
}

// round 8
// speedup vs baseline: 1.6496x; 1.1819x over previous
#include <cuda_runtime.h>
#include <cuda_bf16.h>
#include <math.h>
#include <stdint.h>

#define BB   32
#define CC   256
#define HCH  14
#define PP   196
#define KCODES 8192
#define COLS 6272
#define BOW_ELEMS (BB*KCODES)
#define CODES_OFF BOW_ELEMS

#define KC 64                  // bf16 per chunk row = 128B (SW128)
#define NCHUNK 24              // 6 terms * (256/64)
#define MT 256                 // M rows per CTA
#define NTT 128                // N cols per CTA
#define A_BYTES (MT*128)       // 32768
#define B_BYTES (NTT*128)      // 16384
#define STAGE (A_BYTES + B_BYTES)   // 49152
#define NSTAGE 3
#define DSMEM (NSTAGE*STAGE + 1024)
#define KSEG (KCODES/MT)       // 32

// ---------------- scratch ----------------
__device__ __nv_bfloat16 g_eh[KCODES*CC], g_em[KCODES*CC], g_el[KCODES*CC];
__device__ __nv_bfloat16 g_fh[COLS*CC],   g_fm[COLS*CC],   g_fl[COLS*CC];
__device__ float g_esq[KCODES];
__device__ float g_fsq[COLS];
__device__ float g_pm[KSEG*COLS];
__device__ float g_ps[KSEG*COLS];
__device__ float g_colm[COLS];
__device__ float g_colr[COLS];

// ---------------- helpers ----------------
__device__ __forceinline__ uint32_t s2u(const void* p) {
    uint32_t a;
    asm("{ .reg .u64 t; cvta.to.shared.u64 t, %1; cvt.u32.u64 %0, t; }" : "=r"(a) : "l"(p));
    return a;
}
#define SWZ(o) ((o) ^ (((o) >> 3) & 0x70))
__device__ __forceinline__ void cp16(uint32_t dst, const void* src) {
    asm volatile("cp.async.cg.shared.global [%0], [%1], 16;" :: "r"(dst), "l"(src));
}
__device__ __forceinline__ void ldsm4(uint32_t* r, uint32_t addr) {
    asm volatile("ldmatrix.sync.aligned.m8n8.x4.shared.b16 {%0,%1,%2,%3}, [%4];"
                 : "=r"(r[0]), "=r"(r[1]), "=r"(r[2]), "=r"(r[3]) : "r"(addr));
}
__device__ __forceinline__ void mma16816(float* c, const uint32_t* a, const uint32_t* b) {
    asm volatile(
        "mma.sync.aligned.m16n8k16.row.col.f32.bf16.bf16.f32 "
        "{%0,%1,%2,%3}, {%4,%5,%6,%7}, {%8,%9}, {%0,%1,%2,%3};"
        : "+f"(c[0]), "+f"(c[1]), "+f"(c[2]), "+f"(c[3])
        : "r"(a[0]), "r"(a[1]), "r"(a[2]), "r"(a[3]), "r"(b[0]), "r"(b[1]));
}

// ---------------- prep: embedding splits + e_sq (fused, warp per row) -------
__global__ void k_prep_emb(const float* __restrict__ emb) {
    int warp = (blockIdx.x * blockDim.x + threadIdx.x) >> 5;
    int lane = threadIdx.x & 31;
    if (warp >= KCODES) return;
    const float* r = emb + (size_t)warp * CC;
    double s = 0.0;
    #pragma unroll
    for (int i = 0; i < CC / 32; i++) {
        int c = lane + i * 32;
        float v = r[c];
        s += (double)v * (double)v;
        __nv_bfloat16 h = __float2bfloat16_rn(v);
        float r1 = v - __bfloat162float(h);
        __nv_bfloat16 m = __float2bfloat16_rn(r1);
        float r2 = r1 - __bfloat162float(m);
        size_t o = (size_t)warp * CC + c;
        g_eh[o] = h; g_em[o] = m; g_el[o] = __float2bfloat16_rn(r2);
    }
    #pragma unroll
    for (int o = 16; o; o >>= 1) s += __shfl_xor_sync(0xFFFFFFFFu, s, o);
    if (lane == 0) g_esq[warp] = (float)s;
}

// crop + transpose features -> [col][c] bf16 splits
__global__ void k_prep_f(const float* __restrict__ feat) {
    __shared__ float tile[32][33];
    int tx = threadIdx.x, ty = threadIdx.y;
    int col = blockIdx.x * 32 + tx;
    int c   = blockIdx.y * 32 + ty;
    int b = col / PP, p = col - b * PP;
    int y = p / HCH + 1, x = p - (y - 1) * HCH + 1;
    tile[ty][tx] = feat[((size_t)(b * CC + c) * 16 + y) * 16 + x];
    __syncthreads();
    int colw = blockIdx.x * 32 + ty;
    int cw   = blockIdx.y * 32 + tx;
    float v = tile[tx][ty];
    __nv_bfloat16 h = __float2bfloat16_rn(v);
    float r1 = v - __bfloat162float(h);
    __nv_bfloat16 m = __float2bfloat16_rn(r1);
    float r2 = r1 - __bfloat162float(m);
    size_t o = (size_t)colw * CC + cw;
    g_fh[o] = h; g_fm[o] = m; g_fl[o] = __float2bfloat16_rn(r2);
}

// f_sq: block per batch, thread = pixel, 4 fp64 accumulators for MLP
__global__ void k_fsq(const float* __restrict__ feat) {
    int b = blockIdx.x, t = threadIdx.x;          // t = y*16+x
    const float* fp = feat + (size_t)b * CC * 256 + t;
    double s0 = 0.0, s1 = 0.0, s2 = 0.0, s3 = 0.0;
    #pragma unroll 16
    for (int c = 0; c < CC; c += 4) {
        float v0 = fp[(size_t)(c + 0) * 256];
        float v1 = fp[(size_t)(c + 1) * 256];
        float v2 = fp[(size_t)(c + 2) * 256];
        float v3 = fp[(size_t)(c + 3) * 256];
        s0 += (double)v0 * v0; s1 += (double)v1 * v1;
        s2 += (double)v2 * v2; s3 += (double)v3 * v3;
    }
    double s = (s0 + s1) + (s2 + s3);
    int y = t >> 4, x = t & 15;
    if (y >= 1 && y <= 14 && x >= 1 && x <= 14)
        g_fsq[b * PP + (y - 1) * HCH + (x - 1)] = (float)s;
}

// ---------------------------------------------------------------------------
// Warp-MMA GEMM: CTA 256(codes) x 128(cols), 16 warps, warp tile 64x32.
// 6-term bf16x3 emulation, 3-stage cp.async pipeline, SW128 smem.
// Epilogue: streaming logits stores + per-(ktile,col) partial (max, sumexp).
// ---------------------------------------------------------------------------
__global__ __launch_bounds__(512, 1) void k_mma(float* __restrict__ out) {
    extern __shared__ char dsm[];
    __shared__ float     s_fsq[NTT];
    __shared__ float     s_esq[MT];
    __shared__ long long s_cbase[NTT];
    __shared__ float     s_rm[4][NTT];
    __shared__ float     s_rs[4][NTT];

    int tid = threadIdx.x, lane = tid & 31, wid = tid >> 5;
    int warp_m = wid >> 2, warp_n = wid & 3;     // warp tile: 64 m x 32 n
    int col0 = blockIdx.x * NTT, krow0 = blockIdx.y * MT;
    float* codes = out + CODES_OFF;
    uint32_t base = (s2u(dsm) + 1023u) & ~1023u;

    if (tid < NTT) {
        int col = col0 + tid;
        s_fsq[tid] = g_fsq[col];
        int b = col / PP, p = col - b * PP;
        s_cbase[tid] = (long long)b * KCODES * PP + p;
    }
    if (tid < MT) s_esq[tid] = g_esq[krow0 + tid];

    float acc[4][4][4];                          // [mi][ni][quad]
    #pragma unroll
    for (int mi = 0; mi < 4; mi++)
        #pragma unroll
        for (int ni = 0; ni < 4; ni++)
            #pragma unroll
            for (int q = 0; q < 4; q++) acc[mi][ni][q] = 0.0f;

    int rA = lane & 15, csA = lane >> 4;
    int rB = ((lane >> 4) << 3) + (lane & 7), csB = (lane >> 3) & 1;

    auto issue = [&](int ch, int buf) {
        int t = ch >> 2, c0 = (ch & 3) * KC;
        int ai = (t == 0) ? 2 : ((t == 2 || t == 3) ? 1 : 0);
        int bi = (t == 1) ? 2 : ((t == 2 || t == 4) ? 1 : 0);
        const __nv_bfloat16* pa = ((ai == 0) ? g_eh : (ai == 1) ? g_em : g_el)
                                  + (size_t)krow0 * CC + c0;
        const __nv_bfloat16* pb = ((bi == 0) ? g_fh : (bi == 1) ? g_fm : g_fl)
                                  + (size_t)col0 * CC + c0;
        uint32_t A0 = base + buf * STAGE, B0 = A0 + A_BYTES;
        #pragma unroll
        for (int i = 0; i < 4; i++) {            // A: 2048 units / 512 thr
            int u = tid + i * 512, r = u >> 3, g = u & 7;
            uint32_t off = (uint32_t)(r * 128 + g * 16);
            cp16(A0 + SWZ(off), pa + (size_t)r * CC + g * 8);
        }
        #pragma unroll
        for (int i = 0; i < 2; i++) {            // B: 1024 units
            int u = tid + i * 512, r = u >> 3, g = u & 7;
            uint32_t off = (uint32_t)(r * 128 + g * 16);
            cp16(B0 + SWZ(off), pb + (size_t)r * CC + g * 8);
        }
        asm volatile("cp.async.commit_group;" ::: "memory");
    };

    issue(0, 0);
    issue(1, 1);

    #pragma unroll 1
    for (int ch = 0; ch < NCHUNK; ++ch) {
        if (ch < NCHUNK - 1) asm volatile("cp.async.wait_group 1;" ::: "memory");
        else                 asm volatile("cp.async.wait_group 0;" ::: "memory");
        __syncthreads();

        uint32_t A0 = base + (ch % NSTAGE) * STAGE, B0 = A0 + A_BYTES;
        #pragma unroll
        for (int s = 0; s < 4; s++) {
            uint32_t b[8];
            {
                uint32_t off = (uint32_t)((warp_n * 32 + rB) * 128 + (2 * s + csB) * 16);
                ldsm4(b, B0 + SWZ(off));
                uint32_t off2 = (uint32_t)((warp_n * 32 + 16 + rB) * 128 + (2 * s + csB) * 16);
                ldsm4(b + 4, B0 + SWZ(off2));
            }
            #pragma unroll
            for (int mi = 0; mi < 4; mi++) {
                uint32_t a[4];
                uint32_t off = (uint32_t)((warp_m * 64 + mi * 16 + rA) * 128 + (2 * s + csA) * 16);
                ldsm4(a, A0 + SWZ(off));
                #pragma unroll
                for (int ni = 0; ni < 4; ni++)
                    mma16816(acc[mi][ni], a, b + 2 * ni);
            }
        }
        if (ch + 2 < NCHUNK) issue(ch + 2, (ch + 2) % NSTAGE);
    }

    // ---- epilogue: streaming logits + partial (max,sumexp) per column ----
    #pragma unroll
    for (int ni = 0; ni < 4; ni++) {
        #pragma unroll
        for (int jj = 0; jj < 2; jj++) {
            int j = warp_n * 32 + ni * 8 + 2 * (lane & 3) + jj;
            float fsq = s_fsq[j];
            long long cb = s_cbase[j];
            float pm = -INFINITY, ps = 0.0f;
            #pragma unroll
            for (int mi = 0; mi < 4; mi++) {
                #pragma unroll
                for (int rr = 0; rr < 2; rr++) {
                    int krel = warp_m * 64 + mi * 16 + (lane >> 2) + rr * 8;
                    float cross = acc[mi][ni][rr * 2 + jj];
                    float tq = __fadd_rn(fsq, __fmul_rn(-2.0f, cross));
                    float d  = __fadd_rn(tq, s_esq[krel]);
                    float l  = __fmul_rn(-30.0f, d);
                    __stcs(&codes[cb + (long long)(krow0 + krel) * PP], l);
                    if (l > pm) { ps = __fmaf_rn(ps, __expf(pm - l), 1.0f); pm = l; }
                    else        { ps += __expf(l - pm); }
                }
            }
            #pragma unroll
            for (int o = 4; o <= 16; o <<= 1) {
                float om = __shfl_xor_sync(0xFFFFFFFFu, pm, o);
                float os = __shfl_xor_sync(0xFFFFFFFFu, ps, o);
                if (om > pm) { ps = ps * __expf(pm - om) + os; pm = om; }
                else         { ps += os * __expf(om - pm); }
            }
            if ((lane >> 2) == 0) { s_rm[warp_m][j] = pm; s_rs[warp_m][j] = ps; }
        }
    }
    __syncthreads();
    if (tid < NTT) {
        float m = -INFINITY, s = 0.0f;
        #pragma unroll
        for (int w = 0; w < 4; w++) {
            float mi = s_rm[w][tid], si = s_rs[w][tid];
            if (mi > m) { s = s * __expf(m - mi) + si; m = mi; }
            else        { s += si * __expf(mi - m); }
        }
        g_pm[blockIdx.y * COLS + col0 + tid] = m;
        g_ps[blockIdx.y * COLS + col0 + tid] = s;
    }
}

// ---------------- merge KSEG partials per column ----------------
__global__ void k_merge() {
    int col = blockIdx.x * 256 + threadIdx.x;
    if (col >= COLS) return;
    float m = -INFINITY, s = 0.0f;
    #pragma unroll 8
    for (int sp = 0; sp < KSEG; sp++) {
        float mi = g_pm[sp * COLS + col], si = g_ps[sp * COLS + col];
        if (mi > m) { s = s * __expf(m - mi) + si; m = mi; }
        else        { s += si * __expf(mi - m); }
    }
    g_colm[col] = m;
    g_colr[col] = 1.0f / s;
}

// ---------------- pass B: rescale + bow max (streaming) ----------------
__global__ void k_phase2(float* __restrict__ out) {
    float* codes = out + CODES_OFF;
    float* bow   = out;
    int b = blockIdx.y, kc = blockIdx.x;
    int warp = threadIdx.x >> 5, lane = threadIdx.x & 31;

    __shared__ float sm[PP];
    __shared__ float sr[PP];
    for (int i = threadIdx.x; i < PP; i += 256) {
        sm[i] = g_colm[b * PP + i];
        sr[i] = g_colr[b * PP + i];
    }
    __syncthreads();

    #pragma unroll 1
    for (int rr = 0; rr < 32; ++rr) {
        int k = kc * 256 + warp * 32 + rr;
        float* row = codes + ((size_t)b * KCODES + k) * PP;
        float mx = 0.0f;
        for (int j = lane; j < PP; j += 32) {
            float l = __ldcs(&row[j]);
            float v = expf(__fadd_rn(l, -sm[j])) * sr[j];
            __stcs(&row[j], v);
            mx = fmaxf(mx, v);
        }
        #pragma unroll
        for (int o = 16; o; o >>= 1) mx = fmaxf(mx, __shfl_xor_sync(0xFFFFFFFFu, mx, o));
        if (lane == 0) bow[(size_t)b * KCODES + k] = mx;
    }
}

__global__ void k_norm(float* __restrict__ out) {
    __shared__ float red[256];
    int b = blockIdx.x;
    float* r = out + (size_t)b * KCODES;
    float s = 0.0f;
    for (int i = threadIdx.x; i < KCODES; i += 256) s += fabsf(r[i]);
    red[threadIdx.x] = s;
    __syncthreads();
    for (int o = 128; o; o >>= 1) {
        if (threadIdx.x < o) red[threadIdx.x] += red[threadIdx.x + o];
        __syncthreads();
    }
    float tot = fmaxf(red[0], 1e-12f);
    for (int i = threadIdx.x; i < KCODES; i += 256) r[i] = r[i] / tot;
}

extern "C" void kernel_launch(void* const* d_in, const int* in_sizes, int n_in,
                              void* d_out, int out_size) {
    const float* feat = (const float*)d_in[0];   // [32,256,16,16]
    const float* emb  = (const float*)d_in[1];   // [8192,256]
    float* out = (float*)d_out;

    cudaFuncSetAttribute(k_mma, cudaFuncAttributeMaxDynamicSharedMemorySize, DSMEM);

    k_prep_emb<<<KCODES / 8, 256>>>(emb);                        // 1
    k_prep_f<<<dim3(COLS / 32, CC / 32), dim3(32, 32)>>>(feat);  // 2
    k_fsq<<<BB, 256>>>(feat);                                    // 3
    k_mma<<<dim3(COLS / NTT, KCODES / MT), 512, DSMEM>>>(out);   // 4 (profiled slot)
    k_merge<<<(COLS + 255) / 256, 256>>>();                      // 5
    k_phase2<<<dim3(KCODES / 256, BB), 256>>>(out);              // 6
    k_norm<<<BB, 256>>>(out);                                    // 7
}

// round 9
// speedup vs baseline: 1.9185x; 1.1630x over previous
#include <cuda_runtime.h>
#include <cuda_bf16.h>
#include <math.h>
#include <stdint.h>

#define BB   32
#define CC   256
#define HCH  14
#define PP   196
#define KCODES 8192
#define COLS 6272
#define BOW_ELEMS (BB*KCODES)
#define CODES_OFF BOW_ELEMS

#define KC 64                  // bf16 per chunk row = 128B (SW128)
#define NCHUNK 24              // 6 terms * (256/64)
#define MT 128                 // M rows per CTA
#define NTT 128                // N cols per CTA
#define A_BYTES (MT*128)       // 16384
#define B_BYTES (NTT*128)      // 16384
#define STAGE (A_BYTES + B_BYTES)   // 32768
#define NSTAGE 3
#define DSMEM (NSTAGE*STAGE + 1024)
#define KSEG (KCODES/MT)       // 64

// ---------------- scratch ----------------
__device__ __nv_bfloat16 g_eh[KCODES*CC], g_em[KCODES*CC], g_el[KCODES*CC];
__device__ __nv_bfloat16 g_fh[COLS*CC],   g_fm[COLS*CC],   g_fl[COLS*CC];
__device__ float g_esq[KCODES];
__device__ float g_fsq[COLS];
__device__ float g_pm[KSEG*COLS];
__device__ float g_ps[KSEG*COLS];
__device__ float g_colm[COLS];
__device__ float g_colr[COLS];

// ---------------- helpers ----------------
__device__ __forceinline__ uint32_t s2u(const void* p) {
    uint32_t a;
    asm("{ .reg .u64 t; cvta.to.shared.u64 t, %1; cvt.u32.u64 %0, t; }" : "=r"(a) : "l"(p));
    return a;
}
#define SWZ(o) ((o) ^ (((o) >> 3) & 0x70))
__device__ __forceinline__ void cp16(uint32_t dst, const void* src) {
    asm volatile("cp.async.cg.shared.global [%0], [%1], 16;" :: "r"(dst), "l"(src));
}
__device__ __forceinline__ void ldsm4(uint32_t* r, uint32_t addr) {
    asm volatile("ldmatrix.sync.aligned.m8n8.x4.shared.b16 {%0,%1,%2,%3}, [%4];"
                 : "=r"(r[0]), "=r"(r[1]), "=r"(r[2]), "=r"(r[3]) : "r"(addr));
}
__device__ __forceinline__ void mma16816(float* c, const uint32_t* a, const uint32_t* b) {
    asm volatile(
        "mma.sync.aligned.m16n8k16.row.col.f32.bf16.bf16.f32 "
        "{%0,%1,%2,%3}, {%4,%5,%6,%7}, {%8,%9}, {%0,%1,%2,%3};"
        : "+f"(c[0]), "+f"(c[1]), "+f"(c[2]), "+f"(c[3])
        : "r"(a[0]), "r"(a[1]), "r"(a[2]), "r"(a[3]), "r"(b[0]), "r"(b[1]));
}

// ---------------- prep: embedding splits + e_sq (fused, warp per row) -------
__global__ void k_prep_emb(const float* __restrict__ emb) {
    int warp = (blockIdx.x * blockDim.x + threadIdx.x) >> 5;
    int lane = threadIdx.x & 31;
    if (warp >= KCODES) return;
    const float* r = emb + (size_t)warp * CC;
    double s = 0.0;
    #pragma unroll
    for (int i = 0; i < CC / 32; i++) {
        int c = lane + i * 32;
        float v = r[c];
        s += (double)v * (double)v;
        __nv_bfloat16 h = __float2bfloat16_rn(v);
        float r1 = v - __bfloat162float(h);
        __nv_bfloat16 m = __float2bfloat16_rn(r1);
        float r2 = r1 - __bfloat162float(m);
        size_t o = (size_t)warp * CC + c;
        g_eh[o] = h; g_em[o] = m; g_el[o] = __float2bfloat16_rn(r2);
    }
    #pragma unroll
    for (int o = 16; o; o >>= 1) s += __shfl_xor_sync(0xFFFFFFFFu, s, o);
    if (lane == 0) g_esq[warp] = (float)s;
}

// crop + transpose features -> [col][c] bf16 splits
__global__ void k_prep_f(const float* __restrict__ feat) {
    __shared__ float tile[32][33];
    int tx = threadIdx.x, ty = threadIdx.y;
    int col = blockIdx.x * 32 + tx;
    int c   = blockIdx.y * 32 + ty;
    int b = col / PP, p = col - b * PP;
    int y = p / HCH + 1, x = p - (y - 1) * HCH + 1;
    tile[ty][tx] = feat[((size_t)(b * CC + c) * 16 + y) * 16 + x];
    __syncthreads();
    int colw = blockIdx.x * 32 + ty;
    int cw   = blockIdx.y * 32 + tx;
    float v = tile[tx][ty];
    __nv_bfloat16 h = __float2bfloat16_rn(v);
    float r1 = v - __bfloat162float(h);
    __nv_bfloat16 m = __float2bfloat16_rn(r1);
    float r2 = r1 - __bfloat162float(m);
    size_t o = (size_t)colw * CC + cw;
    g_fh[o] = h; g_fm[o] = m; g_fl[o] = __float2bfloat16_rn(r2);
}

// f_sq: block per batch, thread = pixel, 4 fp64 accumulators for MLP
__global__ void k_fsq(const float* __restrict__ feat) {
    int b = blockIdx.x, t = threadIdx.x;          // t = y*16+x
    const float* fp = feat + (size_t)b * CC * 256 + t;
    double s0 = 0.0, s1 = 0.0, s2 = 0.0, s3 = 0.0;
    #pragma unroll 16
    for (int c = 0; c < CC; c += 4) {
        float v0 = fp[(size_t)(c + 0) * 256];
        float v1 = fp[(size_t)(c + 1) * 256];
        float v2 = fp[(size_t)(c + 2) * 256];
        float v3 = fp[(size_t)(c + 3) * 256];
        s0 += (double)v0 * v0; s1 += (double)v1 * v1;
        s2 += (double)v2 * v2; s3 += (double)v3 * v3;
    }
    double s = (s0 + s1) + (s2 + s3);
    int y = t >> 4, x = t & 15;
    if (y >= 1 && y <= 14 && x >= 1 && x <= 14)
        g_fsq[b * PP + (y - 1) * HCH + (x - 1)] = (float)s;
}

// ---------------------------------------------------------------------------
// Warp-MMA GEMM: CTA 128(codes) x 128(cols), 8 warps, warp tile 64x32,
// 2 CTAs/SM. 6-term bf16x3 emulation, 3-stage cp.async pipeline, SW128 smem.
// Epilogue: streaming logits stores + per-(ktile,col) partial (max, sumexp).
// ---------------------------------------------------------------------------
__global__ __launch_bounds__(256, 2) void k_mma(float* __restrict__ out) {
    extern __shared__ char dsm[];
    __shared__ float     s_fsq[NTT];
    __shared__ float     s_esq[MT];
    __shared__ long long s_cbase[NTT];
    __shared__ float     s_rm[2][NTT];
    __shared__ float     s_rs[2][NTT];

    int tid = threadIdx.x, lane = tid & 31, wid = tid >> 5;
    int warp_m = wid >> 2, warp_n = wid & 3;     // warp tile: 64 m x 32 n
    int col0 = blockIdx.x * NTT, krow0 = blockIdx.y * MT;
    float* codes = out + CODES_OFF;
    uint32_t base = (s2u(dsm) + 1023u) & ~1023u;

    if (tid < NTT) {
        int col = col0 + tid;
        s_fsq[tid] = g_fsq[col];
        int b = col / PP, p = col - b * PP;
        s_cbase[tid] = (long long)b * KCODES * PP + p;
    }
    if (tid < MT) s_esq[tid] = g_esq[krow0 + tid];

    float acc[4][4][4];                          // [mi][ni][quad]
    #pragma unroll
    for (int mi = 0; mi < 4; mi++)
        #pragma unroll
        for (int ni = 0; ni < 4; ni++)
            #pragma unroll
            for (int q = 0; q < 4; q++) acc[mi][ni][q] = 0.0f;

    int rA = lane & 15, csA = lane >> 4;
    int rB = ((lane >> 4) << 3) + (lane & 7), csB = (lane >> 3) & 1;

    // hoisted per-thread load addressing (invariant across chunks)
    uint32_t dstoff[4];
    size_t   srcoff[4];
    #pragma unroll
    for (int i = 0; i < 4; i++) {
        int u = tid + i * 256, r = u >> 3, g = u & 7;
        dstoff[i] = SWZ((uint32_t)(r * 128 + g * 16));
        srcoff[i] = (size_t)r * CC + g * 8;
    }

    auto issue = [&](int ch, int buf) {
        int t = ch >> 2, c0 = (ch & 3) * KC;
        int ai = (t == 0) ? 2 : ((t == 2 || t == 3) ? 1 : 0);
        int bi = (t == 1) ? 2 : ((t == 2 || t == 4) ? 1 : 0);
        const __nv_bfloat16* pa = ((ai == 0) ? g_eh : (ai == 1) ? g_em : g_el)
                                  + (size_t)krow0 * CC + c0;
        const __nv_bfloat16* pb = ((bi == 0) ? g_fh : (bi == 1) ? g_fm : g_fl)
                                  + (size_t)col0 * CC + c0;
        uint32_t A0 = base + buf * STAGE, B0 = A0 + A_BYTES;
        #pragma unroll
        for (int i = 0; i < 4; i++) cp16(A0 + dstoff[i], pa + srcoff[i]);
        #pragma unroll
        for (int i = 0; i < 4; i++) cp16(B0 + dstoff[i], pb + srcoff[i]);
        asm volatile("cp.async.commit_group;" ::: "memory");
    };

    issue(0, 0);
    issue(1, 1);

    #pragma unroll 1
    for (int ch = 0; ch < NCHUNK; ++ch) {
        if (ch < NCHUNK - 1) asm volatile("cp.async.wait_group 1;" ::: "memory");
        else                 asm volatile("cp.async.wait_group 0;" ::: "memory");
        __syncthreads();

        uint32_t A0 = base + (ch % NSTAGE) * STAGE, B0 = A0 + A_BYTES;
        #pragma unroll
        for (int s = 0; s < 4; s++) {
            uint32_t b[8];
            {
                uint32_t off = (uint32_t)((warp_n * 32 + rB) * 128 + (2 * s + csB) * 16);
                ldsm4(b, B0 + SWZ(off));
                uint32_t off2 = (uint32_t)((warp_n * 32 + 16 + rB) * 128 + (2 * s + csB) * 16);
                ldsm4(b + 4, B0 + SWZ(off2));
            }
            #pragma unroll
            for (int mi = 0; mi < 4; mi++) {
                uint32_t a[4];
                uint32_t off = (uint32_t)((warp_m * 64 + mi * 16 + rA) * 128 + (2 * s + csA) * 16);
                ldsm4(a, A0 + SWZ(off));
                #pragma unroll
                for (int ni = 0; ni < 4; ni++)
                    mma16816(acc[mi][ni], a, b + 2 * ni);
            }
        }
        if (ch + 2 < NCHUNK) issue(ch + 2, (ch + 2) % NSTAGE);
    }

    // ---- epilogue: streaming logits + partial (max,sumexp) per column ----
    #pragma unroll
    for (int ni = 0; ni < 4; ni++) {
        #pragma unroll
        for (int jj = 0; jj < 2; jj++) {
            int j = warp_n * 32 + ni * 8 + 2 * (lane & 3) + jj;
            float fsq = s_fsq[j];
            long long cb = s_cbase[j];
            float pm = -INFINITY, ps = 0.0f;
            #pragma unroll
            for (int mi = 0; mi < 4; mi++) {
                #pragma unroll
                for (int rr = 0; rr < 2; rr++) {
                    int krel = warp_m * 64 + mi * 16 + (lane >> 2) + rr * 8;
                    float cross = acc[mi][ni][rr * 2 + jj];
                    float tq = __fadd_rn(fsq, __fmul_rn(-2.0f, cross));
                    float d  = __fadd_rn(tq, s_esq[krel]);
                    float l  = __fmul_rn(-30.0f, d);
                    __stcs(&codes[cb + (long long)(krow0 + krel) * PP], l);
                    if (l > pm) { ps = __fmaf_rn(ps, __expf(pm - l), 1.0f); pm = l; }
                    else        { ps += __expf(l - pm); }
                }
            }
            #pragma unroll
            for (int o = 4; o <= 16; o <<= 1) {
                float om = __shfl_xor_sync(0xFFFFFFFFu, pm, o);
                float os = __shfl_xor_sync(0xFFFFFFFFu, ps, o);
                if (om > pm) { ps = ps * __expf(pm - om) + os; pm = om; }
                else         { ps += os * __expf(om - pm); }
            }
            if ((lane >> 2) == 0) { s_rm[warp_m][j] = pm; s_rs[warp_m][j] = ps; }
        }
    }
    __syncthreads();
    if (tid < NTT) {
        float m = -INFINITY, s = 0.0f;
        #pragma unroll
        for (int w = 0; w < 2; w++) {
            float mi = s_rm[w][tid], si = s_rs[w][tid];
            if (mi > m) { s = s * __expf(m - mi) + si; m = mi; }
            else        { s += si * __expf(mi - m); }
        }
        g_pm[blockIdx.y * COLS + col0 + tid] = m;
        g_ps[blockIdx.y * COLS + col0 + tid] = s;
    }
}

// ---------------- merge KSEG partials per column ----------------
__global__ void k_merge() {
    int col = blockIdx.x * 256 + threadIdx.x;
    if (col >= COLS) return;
    float m = -INFINITY, s = 0.0f;
    #pragma unroll 8
    for (int sp = 0; sp < KSEG; sp++) {
        float mi = g_pm[sp * COLS + col], si = g_ps[sp * COLS + col];
        if (mi > m) { s = s * __expf(m - mi) + si; m = mi; }
        else        { s += si * __expf(mi - m); }
    }
    g_colm[col] = m;
    g_colr[col] = 1.0f / s;
}

// ---------------- pass B: rescale + bow max (streaming) ----------------
__global__ void k_phase2(float* __restrict__ out) {
    float* codes = out + CODES_OFF;
    float* bow   = out;
    int b = blockIdx.y, kc = blockIdx.x;
    int warp = threadIdx.x >> 5, lane = threadIdx.x & 31;

    __shared__ float sm[PP];
    __shared__ float sr[PP];
    for (int i = threadIdx.x; i < PP; i += 256) {
        sm[i] = g_colm[b * PP + i];
        sr[i] = g_colr[b * PP + i];
    }
    __syncthreads();

    #pragma unroll 1
    for (int rr = 0; rr < 32; ++rr) {
        int k = kc * 256 + warp * 32 + rr;
        float* row = codes + ((size_t)b * KCODES + k) * PP;
        float mx = 0.0f;
        for (int j = lane; j < PP; j += 32) {
            float l = __ldcs(&row[j]);
            float v = expf(__fadd_rn(l, -sm[j])) * sr[j];
            __stcs(&row[j], v);
            mx = fmaxf(mx, v);
        }
        #pragma unroll
        for (int o = 16; o; o >>= 1) mx = fmaxf(mx, __shfl_xor_sync(0xFFFFFFFFu, mx, o));
        if (lane == 0) bow[(size_t)b * KCODES + k] = mx;
    }
}

__global__ void k_norm(float* __restrict__ out) {
    __shared__ float red[256];
    int b = blockIdx.x;
    float* r = out + (size_t)b * KCODES;
    float s = 0.0f;
    for (int i = threadIdx.x; i < KCODES; i += 256) s += fabsf(r[i]);
    red[threadIdx.x] = s;
    __syncthreads();
    for (int o = 128; o; o >>= 1) {
        if (threadIdx.x < o) red[threadIdx.x] += red[threadIdx.x + o];
        __syncthreads();
    }
    float tot = fmaxf(red[0], 1e-12f);
    for (int i = threadIdx.x; i < KCODES; i += 256) r[i] = r[i] / tot;
}

extern "C" void kernel_launch(void* const* d_in, const int* in_sizes, int n_in,
                              void* d_out, int out_size) {
    const float* feat = (const float*)d_in[0];   // [32,256,16,16]
    const float* emb  = (const float*)d_in[1];   // [8192,256]
    float* out = (float*)d_out;

    cudaFuncSetAttribute(k_mma, cudaFuncAttributeMaxDynamicSharedMemorySize, DSMEM);

    k_prep_emb<<<KCODES / 8, 256>>>(emb);                        // 1
    k_prep_f<<<dim3(COLS / 32, CC / 32), dim3(32, 32)>>>(feat);  // 2
    k_fsq<<<BB, 256>>>(feat);                                    // 3
    k_mma<<<dim3(COLS / NTT, KCODES / MT), 256, DSMEM>>>(out);   // 4 (profiled slot)
    k_merge<<<(COLS + 255) / 256, 256>>>();                      // 5
    k_phase2<<<dim3(KCODES / 256, BB), 256>>>(out);              // 6
    k_norm<<<BB, 256>>>(out);                                    // 7
}